// round 17
// baseline (speedup 1.0000x reference)
#include <cuda_runtime.h>

// QuadraticProjectionLoss — single-wave fused kernel, cooperative M-build
//   B=8192, V=8, J=32
//   inputs: K [B,V,3,3] f32, cam_preds [B,V,3,4] f32,
//           kps_world_pred [B,J,3] f32, initial_keypoints [B,V,J,2] f32
//   output: scalar f32
//
// Grid 1024 x 256 (one wave at occ 7). Block = 8 batches (two 4-batch chunks).
// M = K(3x3)@cam(3x4) is built ONCE per (batch,view) cooperatively in smem
// (it was previously recomputed identically by all 8 lanes of a view, twice).
// Hot loop reads M via 3 broadcast LDS128; K/cam never enter the hot path.
// Smooth-MSE select uses the exact identity d' = min(d, d^0.1 * 100^0.9).

#define BB 8192
#define VV 8
#define JJ 32
#define NBLK 1024
#define POW_C 63.095734448019324f    // 100^0.9

__device__ __align__(16) float g_partials[NBLK];
__device__ unsigned g_count = 0;     // self-resetting completion counter

__global__ __launch_bounds__(256, 7) void qpl_fused(
    const float* __restrict__ K_g,
    const float* __restrict__ cam_g,
    const float* __restrict__ kps_g,
    const float* __restrict__ init_g,
    float* __restrict__ out)
{
    const int tid  = threadIdx.x;
    const int wid  = tid >> 5;
    const int lane = tid & 31;
    const int bi   = wid >> 1;                       // batch within chunk (0..3)
    const int v    = ((wid & 1) << 2) + (lane >> 3); // view 0..7
    const int g    = lane & 7;                       // kp group (4 kps)

    // ---- shared staging ----
    __shared__ float4 s_kps4[192];                   // 8 batches * 24 float4
    __shared__ float4 s_cam4[192];                   // 8 batches * 24 float4
    __shared__ float  s_K[768];                      // 64 views * 12 (9 used)
    __shared__ __align__(16) float s_M[768];         // 64 views * 12
    __shared__ float  sh[8];
    __shared__ float  ws[8];
    __shared__ bool   isLast;

    const size_t b0 = (size_t)blockIdx.x * 8;
    if (tid < 192) {
        s_kps4[tid] = reinterpret_cast<const float4*>(kps_g + b0 * (JJ * 3))[tid];
        s_cam4[tid] = reinterpret_cast<const float4*>(cam_g + b0 * (VV * 12))[tid];
    }
    #pragma unroll
    for (int it = 0; it < 3; it++) {
        int i = tid + it * 256;                      // 576 K floats -> padded slots
        if (i < 576) {
            int q = i / 9, r = i - q * 9;
            s_K[q * 12 + r] = K_g[b0 * (VV * 9) + i];
        }
    }
    __syncthreads();

    // ---- cooperative M build: thread t -> (bv = t/3, row r = t%3) ----
    if (tid < 192) {
        const int bv = tid / 3, r = tid - bv * 3;
        const float* kr = s_K + bv * 12 + r * 3;
        const float a0 = kr[0], a1 = kr[1], a2 = kr[2];
        const float* cb = reinterpret_cast<const float*>(s_cam4) + bv * 12;
        float* mrow = s_M + bv * 12 + r * 4;
        #pragma unroll
        for (int c = 0; c < 4; c++)
            mrow[c] = fmaf(a0, cb[c], fmaf(a1, cb[4 + c], a2 * cb[8 + c]));
    }
    __syncthreads();

    float loss_acc = 0.0f;

    #pragma unroll 1
    for (int cc = 0; cc < 2; cc++) {
        const int bc = cc * 4 + bi;                  // batch within block (0..7)
        const size_t b = b0 + bc;
        const int bv = bc * 8 + v;

        // init keypoints: direct DRAM stream
        const float4* i4 = reinterpret_cast<const float4*>(
            init_g + ((b * VV + v) * JJ + g * 4) * 2);
        const float4 iA = i4[0], iB = i4[1];

        const float4 kA = s_kps4[bc * 24 + g * 3 + 0];
        const float4 kB = s_kps4[bc * 24 + g * 3 + 1];
        const float4 kC = s_kps4[bc * 24 + g * 3 + 2];

        // M rows: broadcast LDS128 (all 8 lanes of a view hit the same addr)
        const float4 M0 = *reinterpret_cast<const float4*>(s_M + bv * 12);
        const float4 M1 = *reinterpret_cast<const float4*>(s_M + bv * 12 + 4);
        const float4 M2 = *reinterpret_cast<const float4*>(s_M + bv * 12 + 8);

        float s_pn = 0.0f, s_in = 0.0f, s_d = 0.0f;

#define KP_STEP(X, Y, Z, IX, IY) do {                                            \
        const float i0_ = fmaf(M0.x, (X), fmaf(M0.y, (Y), fmaf(M0.z, (Z), M0.w))); \
        const float i1_ = fmaf(M1.x, (X), fmaf(M1.y, (Y), fmaf(M1.z, (Z), M1.w))); \
        const float i2_ = fmaf(M2.x, (X), fmaf(M2.y, (Y), fmaf(M2.z, (Z), M2.w))); \
        const float inv_ = __fdividef(1.0f, i2_);                                \
        const float px_ = i0_ * inv_;                                            \
        const float py_ = i1_ * inv_;                                            \
        s_pn = fmaf(px_, px_, fmaf(py_, py_, s_pn));                             \
        s_in = fmaf((IX), (IX), fmaf((IY), (IY), s_in));                         \
        float dx_ = (px_ - (IX)) * 0.1f; dx_ *= dx_;                             \
        float dy_ = (py_ - (IY)) * 0.1f; dy_ *= dy_;                             \
        dx_ = fminf(dx_, __powf(dx_, 0.1f) * POW_C);                             \
        dy_ = fminf(dy_, __powf(dy_, 0.1f) * POW_C);                             \
        s_d += dx_ + dy_;                                                        \
    } while (0)

        KP_STEP(kA.x, kA.y, kA.z, iA.x, iA.y);
        KP_STEP(kA.w, kB.x, kB.y, iA.z, iA.w);
        KP_STEP(kB.z, kB.w, kC.x, iB.x, iB.y);
        KP_STEP(kC.y, kC.z, kC.w, iB.z, iB.w);
#undef KP_STEP

        // reduce over g (lane bits 0..2 = same view)
        #pragma unroll
        for (int o = 1; o <= 4; o <<= 1) {
            s_pn += __shfl_xor_sync(0xffffffffu, s_pn, o);
            s_in += __shfl_xor_sync(0xffffffffu, s_in, o);
            s_d  += __shfl_xor_sync(0xffffffffu, s_d,  o);
        }

        const float penal = fabsf(sqrtf(s_pn) * rsqrtf(s_in) - 1.0f);
        float loss = 0.5f * s_d * penal;

        // sum this warp's 4 views (lane bits 3,4)
        loss += __shfl_xor_sync(0xffffffffu, loss, 8);
        loss += __shfl_xor_sync(0xffffffffu, loss, 16);

        loss_acc += loss;                            // lane 0's value is used
    }

    if (lane == 0) sh[wid] = loss_acc;
    __syncthreads();

    if (tid == 0) {
        float t = 0.0f;
        #pragma unroll
        for (int i = 0; i < 8; i++) t += sh[i];      // fixed order
        g_partials[blockIdx.x] = t;
        __threadfence();
        unsigned old = atomicAdd(&g_count, 1u);
        isLast = (old == (unsigned)(gridDim.x - 1));
    }
    __syncthreads();

    // ---- last block: deterministic float shuffle-tree over 1024 partials ----
    if (isLast) {
        const float4 p = reinterpret_cast<const float4*>(g_partials)[tid];
        float a = ((p.x + p.y) + p.z) + p.w;         // fixed order
        #pragma unroll
        for (int o = 16; o; o >>= 1)
            a += __shfl_xor_sync(0xffffffffu, a, o);
        if (lane == 0) ws[wid] = a;
        __syncthreads();
        if (wid == 0) {
            float w = (lane < 8) ? ws[lane] : 0.0f;
            w += __shfl_xor_sync(0xffffffffu, w, 1);
            w += __shfl_xor_sync(0xffffffffu, w, 2);
            w += __shfl_xor_sync(0xffffffffu, w, 4);
            if (lane == 0) {
                out[0] = w * (1.0f / 65536.0f);      // / (B*V), exact pow2
                g_count = 0;                         // reset for next graph replay
            }
        }
    }
}

extern "C" void kernel_launch(void* const* d_in, const int* in_sizes, int n_in,
                              void* d_out, int out_size)
{
    const float* K    = (const float*)d_in[0];
    const float* cam  = (const float*)d_in[1];
    const float* kps  = (const float*)d_in[2];
    const float* init = (const float*)d_in[3];

    qpl_fused<<<NBLK, 256>>>(K, cam, kps, init, (float*)d_out);
}